// round 4
// baseline (speedup 1.0000x reference)
#include <cuda_runtime.h>
#include <math.h>
#include <stdint.h>

// Problem constants
#define BB   16
#define NN   2048
#define CIN  64
#define CC   256
#define MTOT (BB*NN)   // 32768

// ---------------- scratch (device globals; no allocation allowed) ----------------
__device__ float g_h[MTOT*CC];
__device__ float g_q[MTOT*CC];
__device__ float g_v[MTOT*CC];
__device__ float g_u[MTOT*CC];
__device__ float g_attn[(size_t)BB*NN*NN];   // 256 MiB attention matrix
__device__ float g_rscale[BB*NN];
__device__ float g_bnscale[3*CC];
__device__ float g_bnshift[3*CC];

// ---------------- BN precompute ----------------
__global__ void bn_prep(const float* __restrict__ g1, const float* __restrict__ b1,
                        const float* __restrict__ m1, const float* __restrict__ v1,
                        const float* __restrict__ g2, const float* __restrict__ b2,
                        const float* __restrict__ m2, const float* __restrict__ v2,
                        const float* __restrict__ g3, const float* __restrict__ b3,
                        const float* __restrict__ m3, const float* __restrict__ v3,
                        const float* __restrict__ bt)
{
    int c = threadIdx.x;
    float s;
    s = g1[c] * rsqrtf(v1[c] + 1e-5f);
    g_bnscale[c]       = s; g_bnshift[c]       = b1[c] - m1[c]*s;
    s = g2[c] * rsqrtf(v2[c] + 1e-5f);
    g_bnscale[256 + c] = s; g_bnshift[256 + c] = b2[c] - m2[c]*s;
    s = g3[c] * rsqrtf(v3[c] + 1e-5f);
    g_bnscale[512 + c] = s; g_bnshift[512 + c] = (bt[c] - m3[c])*s + b3[c];
}

__device__ __forceinline__ uint32_t cvt_tf32(float x) {
    uint32_t u;
    asm("cvt.rna.tf32.f32 %0, %1;" : "=r"(u) : "f"(x));
    return u;
}

__device__ __forceinline__ uint32_t smem_u32(const void* p) {
    return (uint32_t)__cvta_generic_to_shared(p);
}

__device__ __forceinline__ void cp_async16(uint32_t dst, const void* src) {
    asm volatile("cp.async.cg.shared.global [%0], [%1], 16;\n" :: "r"(dst), "l"(src));
}

// ---------------- tensor-core tiled GEMM (tf32 mma.sync, cp.async 2-stage) -------
// C[m,n] = sum_k opA(A)[m,k] * opB(B)[n,k]
//   ATRANS=false: opA(A)[m,k] = A[m*lda + k];  ATRANS=true: A[k*lda + m]
//   BTRANS similarly.
// BM=BN=128, BK=16; 256 threads = 8 warps, each 64x32 via 4x4 m16n8k8 (2 k8 steps).
// smem holds raw fp32 (cp.async); tf32 conversion at fragment load.
//   non-trans operand: [row][k]  stride 20
//   trans operand:     [k][row]  stride 136
// EPI: 0 plain; 1 relu(acc*p0[c]+p1[c]); 2 acc+p0[c]; 4 p2[r,c] - acc*p0[z*NN+r]
template<int EPI, bool ATRANS, bool BTRANS>
__global__ __launch_bounds__(256, 2)
void gemm_tc(const float* __restrict__ A, const float* __restrict__ B,
             float* __restrict__ C, int K,
             int lda, int ldb, int ldc,
             long long sA, long long sB, long long sC,
             const float* __restrict__ p0, const float* __restrict__ p1,
             const float* __restrict__ p2)
{
    __shared__ __align__(16) float As[2][2560];
    __shared__ __align__(16) float Bs[2][2560];

    const int z = blockIdx.z;
    A += (long long)z * sA;
    B += (long long)z * sB;

    const int t    = threadIdx.x;
    const int lane = t & 31;
    const int wid  = t >> 5;
    const int wm   = wid >> 2;      // 0..1
    const int wn   = wid & 3;       // 0..3
    const int grp  = lane >> 2;     // 0..7
    const int qid  = lane & 3;      // 0..3
    const int m0   = blockIdx.y * 128;
    const int n0   = blockIdx.x * 128;

    // per-thread load indices (2 x float4 per tile per operand)
    const int idx0 = t, idx1 = t + 256;

    float acc[4][4][4];
#pragma unroll
    for (int i = 0; i < 4; i++)
#pragma unroll
        for (int j = 0; j < 4; j++)
#pragma unroll
            for (int e = 0; e < 4; e++) acc[i][j][e] = 0.f;

    // ---- tile-issue helper (macro to keep everything inlined) ----
#define ISSUE_TILE(k0, buf)                                                        \
    {                                                                              \
        /* A */                                                                    \
        if (!ATRANS) {                                                             \
            int r0_ = idx0 >> 2, kq0_ = idx0 & 3;                                  \
            int r1_ = idx1 >> 2, kq1_ = idx1 & 3;                                  \
            cp_async16(smem_u32(&As[buf][r0_ * 20 + kq0_ * 4]),                    \
                       &A[(long long)(m0 + r0_) * lda + (k0) + kq0_ * 4]);         \
            cp_async16(smem_u32(&As[buf][r1_ * 20 + kq1_ * 4]),                    \
                       &A[(long long)(m0 + r1_) * lda + (k0) + kq1_ * 4]);         \
        } else {                                                                   \
            int k0_ = idx0 >> 5, m0q_ = idx0 & 31;                                 \
            int k1_ = idx1 >> 5, m1q_ = idx1 & 31;                                 \
            cp_async16(smem_u32(&As[buf][k0_ * 136 + m0q_ * 4]),                   \
                       &A[(long long)((k0) + k0_) * lda + m0 + m0q_ * 4]);         \
            cp_async16(smem_u32(&As[buf][k1_ * 136 + m1q_ * 4]),                   \
                       &A[(long long)((k0) + k1_) * lda + m0 + m1q_ * 4]);         \
        }                                                                          \
        /* B */                                                                    \
        if (!BTRANS) {                                                             \
            int r0_ = idx0 >> 2, kq0_ = idx0 & 3;                                  \
            int r1_ = idx1 >> 2, kq1_ = idx1 & 3;                                  \
            cp_async16(smem_u32(&Bs[buf][r0_ * 20 + kq0_ * 4]),                    \
                       &B[(long long)(n0 + r0_) * ldb + (k0) + kq0_ * 4]);         \
            cp_async16(smem_u32(&Bs[buf][r1_ * 20 + kq1_ * 4]),                    \
                       &B[(long long)(n0 + r1_) * ldb + (k0) + kq1_ * 4]);         \
        } else {                                                                   \
            int k0_ = idx0 >> 5, n0q_ = idx0 & 31;                                 \
            int k1_ = idx1 >> 5, n1q_ = idx1 & 31;                                 \
            cp_async16(smem_u32(&Bs[buf][k0_ * 136 + n0q_ * 4]),                   \
                       &B[(long long)((k0) + k0_) * ldb + n0 + n0q_ * 4]);         \
            cp_async16(smem_u32(&Bs[buf][k1_ * 136 + n1q_ * 4]),                   \
                       &B[(long long)((k0) + k1_) * ldb + n0 + n1q_ * 4]);         \
        }                                                                          \
        asm volatile("cp.async.commit_group;\n");                                  \
    }

    // prologue: load tile 0 into buffer 0
    ISSUE_TILE(0, 0)

    int buf = 0;
    for (int k0 = 0; k0 < K; k0 += 16, buf ^= 1) {
        const bool have_next = (k0 + 16) < K;
        if (have_next) ISSUE_TILE(k0 + 16, buf ^ 1)

        if (have_next) asm volatile("cp.async.wait_group 1;\n");
        else           asm volatile("cp.async.wait_group 0;\n");
        __syncthreads();

        const float* Ab = As[buf];
        const float* Bb = Bs[buf];

#pragma unroll
        for (int ks = 0; ks < 16; ks += 8) {
            uint32_t a[4][4], b[4][2];
#pragma unroll
            for (int i = 0; i < 4; i++) {
                int rb = wm * 64 + i * 16 + grp;
                if (!ATRANS) {
                    a[i][0] = cvt_tf32(Ab[(rb    ) * 20 + ks + qid]);
                    a[i][1] = cvt_tf32(Ab[(rb + 8) * 20 + ks + qid]);
                    a[i][2] = cvt_tf32(Ab[(rb    ) * 20 + ks + 4 + qid]);
                    a[i][3] = cvt_tf32(Ab[(rb + 8) * 20 + ks + 4 + qid]);
                } else {
                    a[i][0] = cvt_tf32(Ab[(ks + qid    ) * 136 + rb]);
                    a[i][1] = cvt_tf32(Ab[(ks + qid    ) * 136 + rb + 8]);
                    a[i][2] = cvt_tf32(Ab[(ks + qid + 4) * 136 + rb]);
                    a[i][3] = cvt_tf32(Ab[(ks + qid + 4) * 136 + rb + 8]);
                }
            }
#pragma unroll
            for (int j = 0; j < 4; j++) {
                int nb = wn * 32 + j * 8 + grp;
                if (!BTRANS) {
                    b[j][0] = cvt_tf32(Bb[nb * 20 + ks + qid]);
                    b[j][1] = cvt_tf32(Bb[nb * 20 + ks + 4 + qid]);
                } else {
                    b[j][0] = cvt_tf32(Bb[(ks + qid    ) * 136 + nb]);
                    b[j][1] = cvt_tf32(Bb[(ks + qid + 4) * 136 + nb]);
                }
            }
#pragma unroll
            for (int i = 0; i < 4; i++)
#pragma unroll
                for (int j = 0; j < 4; j++) {
                    asm volatile(
                        "mma.sync.aligned.m16n8k8.row.col.f32.tf32.tf32.f32 "
                        "{%0,%1,%2,%3}, {%4,%5,%6,%7}, {%8,%9}, {%0,%1,%2,%3};\n"
                        : "+f"(acc[i][j][0]), "+f"(acc[i][j][1]),
                          "+f"(acc[i][j][2]), "+f"(acc[i][j][3])
                        : "r"(a[i][0]), "r"(a[i][1]), "r"(a[i][2]), "r"(a[i][3]),
                          "r"(b[j][0]), "r"(b[j][1]));
                }
        }
        __syncthreads();   // protect buf^1 (being computed next) from overwrite
    }
#undef ISSUE_TILE

    // ---- epilogue ----
    float* Cz = C + (long long)z * sC;
#pragma unroll
    for (int i = 0; i < 4; i++) {
        int r0 = m0 + wm * 64 + i * 16 + grp;
        int r1 = r0 + 8;
#pragma unroll
        for (int j = 0; j < 4; j++) {
            int c = n0 + wn * 32 + j * 8 + qid * 2;
            float d0 = acc[i][j][0], d1 = acc[i][j][1];
            float d2 = acc[i][j][2], d3 = acc[i][j][3];
            float2 o0, o1;
            if (EPI == 0) {
                o0 = make_float2(d0, d1);
                o1 = make_float2(d2, d3);
            } else if (EPI == 1) {
                float s0 = p0[c], s1 = p0[c+1], h0 = p1[c], h1 = p1[c+1];
                o0.x = fmaxf(d0 * s0 + h0, 0.f);
                o0.y = fmaxf(d1 * s1 + h1, 0.f);
                o1.x = fmaxf(d2 * s0 + h0, 0.f);
                o1.y = fmaxf(d3 * s1 + h1, 0.f);
            } else if (EPI == 2) {
                float h0 = p0[c], h1 = p0[c+1];
                o0 = make_float2(d0 + h0, d1 + h1);
                o1 = make_float2(d2 + h0, d3 + h1);
            } else { // EPI == 4 : u = h - acc*rscale[row]
                float rsa = p0[z * NN + r0];
                float rsb = p0[z * NN + r1];
                const float* hpz = p2 + (long long)z * sC;
                o0.x = hpz[(long long)r0 * ldc + c    ] - d0 * rsa;
                o0.y = hpz[(long long)r0 * ldc + c + 1] - d1 * rsa;
                o1.x = hpz[(long long)r1 * ldc + c    ] - d2 * rsb;
                o1.y = hpz[(long long)r1 * ldc + c + 1] - d3 * rsb;
            }
            *(float2*)&Cz[(long long)r0 * ldc + c] = o0;
            *(float2*)&Cz[(long long)r1 * ldc + c] = o1;
        }
    }
}

// ---------------- softmax over last dim, one block per row (2048 elems) ----------
__global__ void softmax_rows(float* __restrict__ attn)
{
    __shared__ float red[256];
    float* p = attn + (long long)blockIdx.x * NN;
    const int t = threadIdx.x;
    float v[8];
    float mx = -1e30f;
#pragma unroll
    for (int i = 0; i < 8; i++) { v[i] = p[t + i*256]; mx = fmaxf(mx, v[i]); }
    red[t] = mx; __syncthreads();
    for (int s = 128; s > 0; s >>= 1) {
        if (t < s) red[t] = fmaxf(red[t], red[t + s]);
        __syncthreads();
    }
    mx = red[0]; __syncthreads();
    float sum = 0.f;
#pragma unroll
    for (int i = 0; i < 8; i++) { v[i] = __expf(v[i] - mx); sum += v[i]; }
    red[t] = sum; __syncthreads();
    for (int s = 128; s > 0; s >>= 1) {
        if (t < s) red[t] += red[t + s];
        __syncthreads();
    }
    float inv = 1.f / red[0];
#pragma unroll
    for (int i = 0; i < 8; i++) p[t + i*256] = v[i] * inv;
}

// ---------------- column sums of attn -> rscale = 1/(eps + colsum) ---------------
__global__ void colsum_k(const float* __restrict__ attn, float* __restrict__ rscale)
{
    const int b = blockIdx.y;
    const int j = blockIdx.x * 256 + threadIdx.x;
    const float* p = attn + (long long)b * NN * NN + j;
    float s0 = 0.f, s1 = 0.f, s2 = 0.f, s3 = 0.f;
    for (int i = 0; i < NN; i += 4) {
        s0 += p[(long long)(i + 0) * NN];
        s1 += p[(long long)(i + 1) * NN];
        s2 += p[(long long)(i + 2) * NN];
        s3 += p[(long long)(i + 3) * NN];
    }
    rscale[b * NN + j] = 1.f / (1e-9f + (s0 + s1) + (s2 + s3));
}

// ---------------- out[b,c,i] = h[b,i,c] + t[b,i,c]  (transpose via smem) ---------
__global__ void trans_add(const float* __restrict__ h, const float* __restrict__ tt,
                          float* __restrict__ out)
{
    __shared__ float sh[32][33];
    const int b  = blockIdx.z;
    const int i0 = blockIdx.x * 32, c0 = blockIdx.y * 32;
    const int tx = threadIdx.x, ty = threadIdx.y;   // 32 x 8
#pragma unroll
    for (int r = 0; r < 4; r++) {
        int i = i0 + ty + r * 8;
        long long idx = ((long long)b * NN + i) * CC + c0 + tx;
        sh[ty + r * 8][tx] = h[idx] + tt[idx];
    }
    __syncthreads();
#pragma unroll
    for (int r = 0; r < 4; r++) {
        int c = c0 + ty + r * 8;
        out[((long long)b * CC + c) * NN + i0 + tx] = sh[tx][ty + r * 8];
    }
}

// ==================================================================================
extern "C" void kernel_launch(void* const* d_in, const int* in_sizes, int n_in,
                              void* d_out, int out_size)
{
    const float* x   = (const float*)d_in[0];
    const float* w1  = (const float*)d_in[1];
    const float* w2  = (const float*)d_in[2];
    const float* wqk = (const float*)d_in[3];
    const float* wv  = (const float*)d_in[4];
    const float* bv  = (const float*)d_in[5];
    const float* wt  = (const float*)d_in[6];
    const float* bt  = (const float*)d_in[7];
    const float* bn1g = (const float*)d_in[8],  *bn1b = (const float*)d_in[9];
    const float* bn1m = (const float*)d_in[10], *bn1v = (const float*)d_in[11];
    const float* bn2g = (const float*)d_in[12], *bn2b = (const float*)d_in[13];
    const float* bn2m = (const float*)d_in[14], *bn2v = (const float*)d_in[15];
    const float* bn3g = (const float*)d_in[16], *bn3b = (const float*)d_in[17];
    const float* bn3m = (const float*)d_in[18], *bn3v = (const float*)d_in[19];

    float *h, *q, *v, *u, *attn, *rscale, *bns, *bnh;
    cudaGetSymbolAddress((void**)&h, g_h);
    cudaGetSymbolAddress((void**)&q, g_q);
    cudaGetSymbolAddress((void**)&v, g_v);
    cudaGetSymbolAddress((void**)&u, g_u);
    cudaGetSymbolAddress((void**)&attn, g_attn);
    cudaGetSymbolAddress((void**)&rscale, g_rscale);
    cudaGetSymbolAddress((void**)&bns, g_bnscale);
    cudaGetSymbolAddress((void**)&bnh, g_bnshift);

    bn_prep<<<1, 256>>>(bn1g, bn1b, bn1m, bn1v,
                        bn2g, bn2b, bn2m, bn2v,
                        bn3g, bn3b, bn3m, bn3v, bt);

    // h1 = relu(bn1(x @ w1^T))   (into q as temp)
    gemm_tc<1, false, false><<<dim3(CC/128, MTOT/128, 1), 256>>>(
        x, w1, q, CIN, CIN, CIN, CC, 0, 0, 0, bns, bnh, nullptr);

    // h = relu(bn2(h1 @ w2^T))
    gemm_tc<1, false, false><<<dim3(CC/128, MTOT/128, 1), 256>>>(
        q, w2, h, CC, CC, CC, CC, 0, 0, 0, bns + 256, bnh + 256, nullptr);

    // q = h @ wqk^T
    gemm_tc<0, false, false><<<dim3(CC/128, MTOT/128, 1), 256>>>(
        h, wqk, q, CC, CC, CC, CC, 0, 0, 0, nullptr, nullptr, nullptr);

    // v = h @ wv^T + bv
    gemm_tc<2, false, false><<<dim3(CC/128, MTOT/128, 1), 256>>>(
        h, wv, v, CC, CC, CC, CC, 0, 0, 0, bv, nullptr, nullptr);

    // energy[b,i,j] = q[b,i,:] . q[b,j,:]   (batched)
    gemm_tc<0, false, false><<<dim3(NN/128, NN/128, BB), 256>>>(
        q, q, attn, CC, CC, CC, NN,
        (long long)NN*CC, (long long)NN*CC, (long long)NN*NN,
        nullptr, nullptr, nullptr);

    // row softmax
    softmax_rows<<<MTOT, 256>>>(attn);

    // column-sum L1 renorm factors
    colsum_k<<<dim3(NN/256, BB), 256>>>(attn, rscale);

    // u[b,j,c] = h - (sum_i attn[i,j] v[i,c]) * rscale[j]
    gemm_tc<4, true, true><<<dim3(CC/128, NN/128, BB), 256>>>(
        attn, v, u, NN, NN, CC, CC,
        (long long)NN*NN, (long long)NN*CC, (long long)NN*CC,
        rscale, nullptr, h);

    // t = relu(bn3(u @ wt^T + bt))   (into q as temp; bt folded into shift)
    gemm_tc<1, false, false><<<dim3(CC/128, MTOT/128, 1), 256>>>(
        u, wt, q, CC, CC, CC, CC, 0, 0, 0, bns + 512, bnh + 512, nullptr);

    // out[b,c,i] = h + t, transposed
    trans_add<<<dim3(NN/32, CC/32, BB), dim3(32, 8)>>>(h, q, (float*)d_out);
}

// round 5
// speedup vs baseline: 1.5853x; 1.5853x over previous
#include <cuda_runtime.h>
#include <math.h>
#include <stdint.h>

// Problem constants
#define BB   16
#define NN   2048
#define CIN  64
#define CC   256
#define MTOT (BB*NN)   // 32768

// ---------------- scratch (device globals; no allocation allowed) ----------------
__device__ float g_h[MTOT*CC];
__device__ float g_q[MTOT*CC];
__device__ float g_v[MTOT*CC];
__device__ float g_u[MTOT*CC];
__device__ float g_attn[(size_t)BB*NN*NN];   // 256 MiB attention matrix
__device__ float g_bnscale[3*CC];
__device__ float g_bnshift[3*CC];

// ---------------- BN precompute ----------------
__global__ void bn_prep(const float* __restrict__ g1, const float* __restrict__ b1,
                        const float* __restrict__ m1, const float* __restrict__ v1,
                        const float* __restrict__ g2, const float* __restrict__ b2,
                        const float* __restrict__ m2, const float* __restrict__ v2,
                        const float* __restrict__ g3, const float* __restrict__ b3,
                        const float* __restrict__ m3, const float* __restrict__ v3,
                        const float* __restrict__ bt)
{
    int c = threadIdx.x;
    float s;
    s = g1[c] * rsqrtf(v1[c] + 1e-5f);
    g_bnscale[c]       = s; g_bnshift[c]       = b1[c] - m1[c]*s;
    s = g2[c] * rsqrtf(v2[c] + 1e-5f);
    g_bnscale[256 + c] = s; g_bnshift[256 + c] = b2[c] - m2[c]*s;
    s = g3[c] * rsqrtf(v3[c] + 1e-5f);
    g_bnscale[512 + c] = s; g_bnshift[512 + c] = (bt[c] - m3[c])*s + b3[c];
}

__device__ __forceinline__ uint32_t cvt_tf32(float x) {
    uint32_t u;
    asm("cvt.rna.tf32.f32 %0, %1;" : "=r"(u) : "f"(x));
    return u;
}

__device__ __forceinline__ float4 cvt4(float4 v) {
    float4 o;
    o.x = __uint_as_float(cvt_tf32(v.x));
    o.y = __uint_as_float(cvt_tf32(v.y));
    o.z = __uint_as_float(cvt_tf32(v.z));
    o.w = __uint_as_float(cvt_tf32(v.w));
    return o;
}

// ---------------- tensor-core tiled GEMM (tf32 mma.sync, register-staged pipe) ----
// C[m,n] = sum_k opA(A)[m,k] * opB(B)[n,k]
//   ATRANS=false: opA(A)[m,k] = A[m*lda + k];  ATRANS=true: A[k*lda + m]
//   BTRANS similarly.
// BM=BN=128, BK=16; 256 threads = 8 warps, each 64x32 via 4x4 m16n8k8 (2 k8 steps).
// smem holds tf32-rounded bit patterns (converted at STS); inner loop = LDS + HMMA.
//   non-trans operand: [row][k]  stride 20
//   trans operand:     [k][row]  stride 136
// EPI: 0 plain; 1 relu(acc*p0[c]+p1[c]); 2 acc+p0[c];
//      4 p2[r,c] - acc*rscale[r]  with rscale computed IN-CTA from raw A (attn)
template<int EPI, bool ATRANS, bool BTRANS>
__global__ __launch_bounds__(256, 2)
void gemm_tc(const float* __restrict__ A, const float* __restrict__ B,
             float* __restrict__ C, int K,
             int lda, int ldb, int ldc,
             long long sA, long long sB, long long sC,
             const float* __restrict__ p0, const float* __restrict__ p1,
             const float* __restrict__ p2)
{
    __shared__ __align__(16) float As[2][2560];
    __shared__ __align__(16) float Bs[2][2560];
    __shared__ float rsc[128];   // EPI4: per-row 1/(eps+colsum)

    const int z = blockIdx.z;
    A += (long long)z * sA;
    B += (long long)z * sB;

    const int t    = threadIdx.x;
    const int lane = t & 31;
    const int wid  = t >> 5;
    const int wm   = wid >> 2;      // 0..1
    const int wn   = wid & 3;       // 0..3
    const int grp  = lane >> 2;     // 0..7
    const int qid  = lane & 3;      // 0..3
    const int m0   = blockIdx.y * 128;
    const int n0   = blockIdx.x * 128;

    const int idx0 = t, idx1 = t + 256;

    // per-thread global base pointers and per-16-k strides
    const long long aStep = ATRANS ? (long long)lda * 16 : 16;
    const long long bStep = BTRANS ? (long long)ldb * 16 : 16;
    const float* aP0 = A + (ATRANS ? (long long)(idx0 >> 5) * lda + m0 + (idx0 & 31) * 4
                                   : (long long)(m0 + (idx0 >> 2)) * lda + (idx0 & 3) * 4);
    const float* aP1 = A + (ATRANS ? (long long)(idx1 >> 5) * lda + m0 + (idx1 & 31) * 4
                                   : (long long)(m0 + (idx1 >> 2)) * lda + (idx1 & 3) * 4);
    const float* bP0 = B + (BTRANS ? (long long)(idx0 >> 5) * ldb + n0 + (idx0 & 31) * 4
                                   : (long long)(n0 + (idx0 >> 2)) * ldb + (idx0 & 3) * 4);
    const float* bP1 = B + (BTRANS ? (long long)(idx1 >> 5) * ldb + n0 + (idx1 & 31) * 4
                                   : (long long)(n0 + (idx1 >> 2)) * ldb + (idx1 & 3) * 4);

    // smem store offsets (fixed per thread)
    const int aS0 = ATRANS ? (idx0 >> 5) * 136 + (idx0 & 31) * 4
                           : (idx0 >> 2) * 20  + (idx0 & 3)  * 4;
    const int aS1 = ATRANS ? (idx1 >> 5) * 136 + (idx1 & 31) * 4
                           : (idx1 >> 2) * 20  + (idx1 & 3)  * 4;
    const int bS0 = BTRANS ? (idx0 >> 5) * 136 + (idx0 & 31) * 4
                           : (idx0 >> 2) * 20  + (idx0 & 3)  * 4;
    const int bS1 = BTRANS ? (idx1 >> 5) * 136 + (idx1 & 31) * 4
                           : (idx1 >> 2) * 20  + (idx1 & 3)  * 4;

    float acc[4][4][4];
#pragma unroll
    for (int i = 0; i < 4; i++)
#pragma unroll
        for (int j = 0; j < 4; j++)
#pragma unroll
            for (int e = 0; e < 4; e++) acc[i][j][e] = 0.f;

    float4 stA0, stA1, stB0, stB1;            // staging registers
    float colacc[4] = {0.f, 0.f, 0.f, 0.f};   // EPI4: partial column sums of attn

#define LDG_TILE(k0)                                                     \
    {                                                                    \
        long long ao = (long long)((k0) / 16) * aStep;                   \
        long long bo = (long long)((k0) / 16) * bStep;                   \
        stA0 = *(const float4*)(aP0 + ao);                               \
        stA1 = *(const float4*)(aP1 + ao);                               \
        stB0 = *(const float4*)(bP0 + bo);                               \
        stB1 = *(const float4*)(bP1 + bo);                               \
    }

#define STS_TILE(buf)                                                    \
    {                                                                    \
        if (EPI == 4) {                                                  \
            colacc[0] += stA0.x + stA1.x;                                \
            colacc[1] += stA0.y + stA1.y;                                \
            colacc[2] += stA0.z + stA1.z;                                \
            colacc[3] += stA0.w + stA1.w;                                \
        }                                                                \
        *(float4*)&As[buf][aS0] = cvt4(stA0);                            \
        *(float4*)&As[buf][aS1] = cvt4(stA1);                            \
        *(float4*)&Bs[buf][bS0] = cvt4(stB0);                            \
        *(float4*)&Bs[buf][bS1] = cvt4(stB1);                            \
    }

    // prologue
    LDG_TILE(0)
    STS_TILE(0)
    __syncthreads();

    int buf = 0;
    for (int k0 = 0; k0 < K; k0 += 16, buf ^= 1) {
        const bool have_next = (k0 + 16) < K;
        if (have_next) LDG_TILE(k0 + 16)

        const float* Ab = As[buf];
        const float* Bb = Bs[buf];
#pragma unroll
        for (int ks = 0; ks < 16; ks += 8) {
            uint32_t a[4][4], b[4][2];
#pragma unroll
            for (int i = 0; i < 4; i++) {
                int rb = wm * 64 + i * 16 + grp;
                if (!ATRANS) {
                    a[i][0] = __float_as_uint(Ab[(rb    ) * 20 + ks + qid]);
                    a[i][1] = __float_as_uint(Ab[(rb + 8) * 20 + ks + qid]);
                    a[i][2] = __float_as_uint(Ab[(rb    ) * 20 + ks + 4 + qid]);
                    a[i][3] = __float_as_uint(Ab[(rb + 8) * 20 + ks + 4 + qid]);
                } else {
                    a[i][0] = __float_as_uint(Ab[(ks + qid    ) * 136 + rb]);
                    a[i][1] = __float_as_uint(Ab[(ks + qid    ) * 136 + rb + 8]);
                    a[i][2] = __float_as_uint(Ab[(ks + qid + 4) * 136 + rb]);
                    a[i][3] = __float_as_uint(Ab[(ks + qid + 4) * 136 + rb + 8]);
                }
            }
#pragma unroll
            for (int j = 0; j < 4; j++) {
                int nb = wn * 32 + j * 8 + grp;
                if (!BTRANS) {
                    b[j][0] = __float_as_uint(Bb[nb * 20 + ks + qid]);
                    b[j][1] = __float_as_uint(Bb[nb * 20 + ks + 4 + qid]);
                } else {
                    b[j][0] = __float_as_uint(Bb[(ks + qid    ) * 136 + nb]);
                    b[j][1] = __float_as_uint(Bb[(ks + qid + 4) * 136 + nb]);
                }
            }
#pragma unroll
            for (int i = 0; i < 4; i++)
#pragma unroll
                for (int j = 0; j < 4; j++) {
                    asm volatile(
                        "mma.sync.aligned.m16n8k8.row.col.f32.tf32.tf32.f32 "
                        "{%0,%1,%2,%3}, {%4,%5,%6,%7}, {%8,%9}, {%0,%1,%2,%3};\n"
                        : "+f"(acc[i][j][0]), "+f"(acc[i][j][1]),
                          "+f"(acc[i][j][2]), "+f"(acc[i][j][3])
                        : "r"(a[i][0]), "r"(a[i][1]), "r"(a[i][2]), "r"(a[i][3]),
                          "r"(b[j][0]), "r"(b[j][1]));
                }
        }
        if (have_next) STS_TILE(buf ^ 1)
        __syncthreads();
    }
#undef LDG_TILE
#undef STS_TILE

    // ---- EPI4: reduce column sums -> rscale in smem ----
    if (EPI == 4) {
        float* red = As[0];   // reuse, 8 x 128
        const int g  = t >> 5;
        const int cq = (t & 31) * 4;
        red[g * 128 + cq + 0] = colacc[0];
        red[g * 128 + cq + 1] = colacc[1];
        red[g * 128 + cq + 2] = colacc[2];
        red[g * 128 + cq + 3] = colacc[3];
        __syncthreads();
        if (t < 128) {
            float s = 0.f;
#pragma unroll
            for (int gg = 0; gg < 8; gg++) s += red[gg * 128 + t];
            rsc[t] = 1.f / (1e-9f + s);
        }
        __syncthreads();
    }

    // ---- epilogue ----
    float* Cz = C + (long long)z * sC;
#pragma unroll
    for (int i = 0; i < 4; i++) {
        int r0 = m0 + wm * 64 + i * 16 + grp;
        int r1 = r0 + 8;
#pragma unroll
        for (int j = 0; j < 4; j++) {
            int c = n0 + wn * 32 + j * 8 + qid * 2;
            float d0 = acc[i][j][0], d1 = acc[i][j][1];
            float d2 = acc[i][j][2], d3 = acc[i][j][3];
            float2 o0, o1;
            if (EPI == 0) {
                o0 = make_float2(d0, d1);
                o1 = make_float2(d2, d3);
            } else if (EPI == 1) {
                float s0 = p0[c], s1 = p0[c+1], h0 = p1[c], h1 = p1[c+1];
                o0.x = fmaxf(d0 * s0 + h0, 0.f);
                o0.y = fmaxf(d1 * s1 + h1, 0.f);
                o1.x = fmaxf(d2 * s0 + h0, 0.f);
                o1.y = fmaxf(d3 * s1 + h1, 0.f);
            } else if (EPI == 2) {
                float h0 = p0[c], h1 = p0[c+1];
                o0 = make_float2(d0 + h0, d1 + h1);
                o1 = make_float2(d2 + h0, d3 + h1);
            } else { // EPI == 4 : u = h - acc*rscale[row]
                float rsa = rsc[r0 - m0];
                float rsb = rsc[r1 - m0];
                const float* hpz = p2 + (long long)z * sC;
                o0.x = hpz[(long long)r0 * ldc + c    ] - d0 * rsa;
                o0.y = hpz[(long long)r0 * ldc + c + 1] - d1 * rsa;
                o1.x = hpz[(long long)r1 * ldc + c    ] - d2 * rsb;
                o1.y = hpz[(long long)r1 * ldc + c + 1] - d3 * rsb;
            }
            *(float2*)&Cz[(long long)r0 * ldc + c] = o0;
            *(float2*)&Cz[(long long)r1 * ldc + c] = o1;
        }
    }
}

// ---------------- softmax over last dim, one block per row (2048 elems) ----------
__global__ void softmax_rows(float* __restrict__ attn)
{
    __shared__ float red[256];
    float* p = attn + (long long)blockIdx.x * NN;
    const int t = threadIdx.x;
    float v[8];
    float mx = -1e30f;
#pragma unroll
    for (int i = 0; i < 8; i++) { v[i] = p[t + i*256]; mx = fmaxf(mx, v[i]); }
    red[t] = mx; __syncthreads();
    for (int s = 128; s > 0; s >>= 1) {
        if (t < s) red[t] = fmaxf(red[t], red[t + s]);
        __syncthreads();
    }
    mx = red[0]; __syncthreads();
    float sum = 0.f;
#pragma unroll
    for (int i = 0; i < 8; i++) { v[i] = __expf(v[i] - mx); sum += v[i]; }
    red[t] = sum; __syncthreads();
    for (int s = 128; s > 0; s >>= 1) {
        if (t < s) red[t] += red[t + s];
        __syncthreads();
    }
    float inv = 1.f / red[0];
#pragma unroll
    for (int i = 0; i < 8; i++) p[t + i*256] = v[i] * inv;
}

// ---------------- out[b,c,i] = h[b,i,c] + t[b,i,c]  (transpose via smem) ---------
__global__ void trans_add(const float* __restrict__ h, const float* __restrict__ tt,
                          float* __restrict__ out)
{
    __shared__ float sh[32][33];
    const int b  = blockIdx.z;
    const int i0 = blockIdx.x * 32, c0 = blockIdx.y * 32;
    const int tx = threadIdx.x, ty = threadIdx.y;   // 32 x 8
#pragma unroll
    for (int r = 0; r < 4; r++) {
        int i = i0 + ty + r * 8;
        long long idx = ((long long)b * NN + i) * CC + c0 + tx;
        sh[ty + r * 8][tx] = h[idx] + tt[idx];
    }
    __syncthreads();
#pragma unroll
    for (int r = 0; r < 4; r++) {
        int c = c0 + ty + r * 8;
        out[((long long)b * CC + c) * NN + i0 + tx] = sh[tx][ty + r * 8];
    }
}

// ==================================================================================
extern "C" void kernel_launch(void* const* d_in, const int* in_sizes, int n_in,
                              void* d_out, int out_size)
{
    const float* x   = (const float*)d_in[0];
    const float* w1  = (const float*)d_in[1];
    const float* w2  = (const float*)d_in[2];
    const float* wqk = (const float*)d_in[3];
    const float* wv  = (const float*)d_in[4];
    const float* bv  = (const float*)d_in[5];
    const float* wt  = (const float*)d_in[6];
    const float* bt  = (const float*)d_in[7];
    const float* bn1g = (const float*)d_in[8],  *bn1b = (const float*)d_in[9];
    const float* bn1m = (const float*)d_in[10], *bn1v = (const float*)d_in[11];
    const float* bn2g = (const float*)d_in[12], *bn2b = (const float*)d_in[13];
    const float* bn2m = (const float*)d_in[14], *bn2v = (const float*)d_in[15];
    const float* bn3g = (const float*)d_in[16], *bn3b = (const float*)d_in[17];
    const float* bn3m = (const float*)d_in[18], *bn3v = (const float*)d_in[19];

    float *h, *q, *v, *u, *attn, *bns, *bnh;
    cudaGetSymbolAddress((void**)&h, g_h);
    cudaGetSymbolAddress((void**)&q, g_q);
    cudaGetSymbolAddress((void**)&v, g_v);
    cudaGetSymbolAddress((void**)&u, g_u);
    cudaGetSymbolAddress((void**)&attn, g_attn);
    cudaGetSymbolAddress((void**)&bns, g_bnscale);
    cudaGetSymbolAddress((void**)&bnh, g_bnshift);

    bn_prep<<<1, 256>>>(bn1g, bn1b, bn1m, bn1v,
                        bn2g, bn2b, bn2m, bn2v,
                        bn3g, bn3b, bn3m, bn3v, bt);

    // h1 = relu(bn1(x @ w1^T))   (into q as temp)
    gemm_tc<1, false, false><<<dim3(CC/128, MTOT/128, 1), 256>>>(
        x, w1, q, CIN, CIN, CIN, CC, 0, 0, 0, bns, bnh, nullptr);

    // h = relu(bn2(h1 @ w2^T))
    gemm_tc<1, false, false><<<dim3(CC/128, MTOT/128, 1), 256>>>(
        q, w2, h, CC, CC, CC, CC, 0, 0, 0, bns + 256, bnh + 256, nullptr);

    // q = h @ wqk^T
    gemm_tc<0, false, false><<<dim3(CC/128, MTOT/128, 1), 256>>>(
        h, wqk, q, CC, CC, CC, CC, 0, 0, 0, nullptr, nullptr, nullptr);

    // v = h @ wv^T + bv
    gemm_tc<2, false, false><<<dim3(CC/128, MTOT/128, 1), 256>>>(
        h, wv, v, CC, CC, CC, CC, 0, 0, 0, bv, nullptr, nullptr);

    // energy[b,i,j] = q[b,i,:] . q[b,j,:]   (batched)
    gemm_tc<0, false, false><<<dim3(NN/128, NN/128, BB), 256>>>(
        q, q, attn, CC, CC, CC, NN,
        (long long)NN*CC, (long long)NN*CC, (long long)NN*NN,
        nullptr, nullptr, nullptr);

    // row softmax
    softmax_rows<<<MTOT, 256>>>(attn);

    // u[b,j,c] = h - (sum_i attn[i,j] v[i,c]) / (eps + sum_i attn[i,j])
    // colsum fused in-kernel from raw staged attn values
    gemm_tc<4, true, true><<<dim3(CC/128, NN/128, BB), 256>>>(
        attn, v, u, NN, NN, CC, CC,
        (long long)NN*NN, (long long)NN*CC, (long long)NN*CC,
        nullptr, nullptr, h);

    // t = relu(bn3(u @ wt^T + bt))   (into q as temp; bt folded into shift)
    gemm_tc<1, false, false><<<dim3(CC/128, MTOT/128, 1), 256>>>(
        u, wt, q, CC, CC, CC, CC, 0, 0, 0, bns + 512, bnh + 512, nullptr);

    // out[b,c,i] = h + t, transposed
    trans_add<<<dim3(NN/32, CC/32, BB), dim3(32, 8)>>>(h, q, (float*)d_out);
}